// round 15
// baseline (speedup 1.0000x reference)
#include <cuda_runtime.h>
#include <cuda_fp16.h>
#include <cstdint>
#include <cstddef>

#define B_   4
#define T_   2048
#define DM   1024
#define H_   16
#define DH   64
#define NTOK (B_ * T_)   // 8192
#define TD3  (3 * DM)

// Scratch (allocation-free rule: __device__ globals)
__device__ __half g_qkv16[(size_t)NTOK * 3 * DM];  // half qkv
__device__ __half g_x16 [(size_t)NTOK * DM];       // half(x), later half(attn out)
__device__ __half g_wq16[(size_t)3 * DM * DM];     // half(w_qkv^T) [3072][1024]
__device__ __half g_wo16[(size_t)DM * DM];         // half(w_out^T) [1024][1024]

__device__ __forceinline__ void cpa16(const void* s, const void* g) {
    uint32_t sa = (uint32_t)__cvta_generic_to_shared(s);
    asm volatile("cp.async.cg.shared.global [%0], [%1], 16;\n" :: "r"(sa), "l"(g));
}
__device__ __forceinline__ void cpa_commit() {
    asm volatile("cp.async.commit_group;\n");
}
__device__ __forceinline__ void cpa_wait0() {
    asm volatile("cp.async.wait_group 0;\n");
}
__device__ __forceinline__ float ex2(float x) {
    float r;
    asm("ex2.approx.f32 %0, %1;" : "=f"(r) : "f"(x));
    return r;
}
__device__ __forceinline__ uint32_t smem_u32(const void* p) {
    uint32_t a;
    asm("{ .reg .u64 t; cvta.to.shared.u64 t, %1; cvt.u32.u64 %0, t; }"
        : "=r"(a) : "l"(p));
    return a;
}
__device__ __forceinline__ void ldsm2(uint32_t& r0, uint32_t& r1, uint32_t a) {
    asm volatile("ldmatrix.sync.aligned.m8n8.x2.shared.b16 {%0,%1}, [%2];"
                 : "=r"(r0), "=r"(r1) : "r"(a));
}
__device__ __forceinline__ void ldsm2t(uint32_t& r0, uint32_t& r1, uint32_t a) {
    asm volatile("ldmatrix.sync.aligned.m8n8.x2.trans.shared.b16 {%0,%1}, [%2];"
                 : "=r"(r0), "=r"(r1) : "r"(a));
}
__device__ __forceinline__ void ldsm4(uint32_t* r, uint32_t a) {
    asm volatile("ldmatrix.sync.aligned.m8n8.x4.shared.b16 {%0,%1,%2,%3}, [%4];"
                 : "=r"(r[0]), "=r"(r[1]), "=r"(r[2]), "=r"(r[3]) : "r"(a));
}
// fp16 MMA m16n8k16 (fp32 acc)
#define MMA_F16(CC, AF, B0, B1)                                               \
    asm volatile(                                                             \
        "mma.sync.aligned.m16n8k16.row.col.f32.f16.f16.f32 "                  \
        "{%0,%1,%2,%3}, {%4,%5,%6,%7}, {%8,%9}, {%0,%1,%2,%3};"               \
        : "+f"((CC)[0]), "+f"((CC)[1]), "+f"((CC)[2]), "+f"((CC)[3])          \
        : "r"((AF)[0]), "r"((AF)[1]), "r"((AF)[2]), "r"((AF)[3]),             \
          "r"(B0), "r"(B1))

// ---------------------------------------------------------------------------
// Pre-passes.
// ---------------------------------------------------------------------------
__global__ __launch_bounds__(256) void cvt_h(const float4* __restrict__ in,
                                             uint2* __restrict__ out)
{
    const size_t i = (size_t)blockIdx.x * 256 + threadIdx.x;
    const float4 v = in[i];
    const __half2 lo = __floats2half2_rn(v.x, v.y);
    const __half2 hi = __floats2half2_rn(v.z, v.w);
    out[i] = make_uint2(*(const uint32_t*)&lo, *(const uint32_t*)&hi);
}
__global__ __launch_bounds__(256) void cvt_ht(const float* __restrict__ in,
                                              __half* __restrict__ out,
                                              int R, int Cc)
{
    __shared__ float t[32][33];
    const int tx = threadIdx.x & 31, ty = threadIdx.x >> 5;
    const int c0 = blockIdx.x << 5, r0 = blockIdx.y << 5;
#pragma unroll
    for (int i = 0; i < 32; i += 8)
        t[ty + i][tx] = in[(size_t)(r0 + ty + i) * Cc + c0 + tx];
    __syncthreads();
#pragma unroll
    for (int i = 0; i < 32; i += 8)
        out[(size_t)(c0 + ty + i) * R + r0 + tx] = __float2half_rn(t[tx][ty + i]);
}

// ---------------------------------------------------------------------------
// FP16 GEMM v2: 128x128 CTA tile, K-CHUNK 64 (half the barrier frequency),
// ldmatrix.x4 fragment loads (6 ldmatrix per k16-step vs 24 LDS.32).
// A/B smem [128][72] halves (row stride 36 u32 == 4 banks: each 8x8 matrix's
// rows occupy 8 disjoint 4-bank groups -> conflict-free). cp.async 2-stage.
// OM=1: fp16 output; OM=0: fp32 output.
// ---------------------------------------------------------------------------
#define HSTR 72
#define HSZ  (128 * HSTR)                   // halves per tile (9216)
#define HGEMM_SMEM (4 * HSZ * 2)            // 73728 bytes (2 CTAs/SM)

template<int OM>
__global__ __launch_bounds__(256, 2) void hgemm(const __half* __restrict__ A,
                                                const __half* __restrict__ Bt,
                                                void* __restrict__ Cv,
                                                int M, int N, int K)
{
    extern __shared__ __half smh[];
    __half* As = smh;                       // [2][128][HSTR]
    __half* Bs = smh + 2 * HSZ;             // [2][128][HSTR]

    const int tid  = threadIdx.x;
    const int lane = tid & 31;
    const int warp = tid >> 5;
    const int wm   = warp >> 1;             // 0..3 (32-row blocks)
    const int wn   = warp & 1;              // 0..1 (64-col blocks)
    const int lr   = lane >> 2;
    const int lc   = lane & 3;
    const int row0 = blockIdx.y << 7;
    const int col0 = blockIdx.x << 7;

    // fill: row = tid>>1 (0..127), 4 segs of 8 halves at (tid&1)*4 + i
    const int frow = tid >> 1;
    const int fs0  = (tid & 1) << 2;

    const __half* Ag = A  + (size_t)(row0 + frow) * K;
    const __half* Bg = Bt + (size_t)(col0 + frow) * K;

    // per-lane ldmatrix address offsets (bytes), within a tile
    const int l7 = lane & 7;
    const int r8 = ((lane >> 3) & 1) << 3;
    // A x4: lanes 0-7:(m+l7,k0) 8-15:(m+8+l7,k0) 16-23:(m+l7,k8) 24-31:(m+8+l7,k8)
    const uint32_t aoff = (uint32_t)(((wm * 32 + l7 + r8) * HSTR +
                                      ((lane >> 4) << 3)) * 2);
    // B x4: lanes 0-7:(n0+l7,k0) 8-15:(n0+l7,k8) 16-23:(n0+8+l7,k0) 24-31:(n0+8+l7,k8)
    const uint32_t boff = (uint32_t)(((wn * 64 + ((lane >> 4) << 3) + l7) * HSTR +
                                      r8) * 2);

    const uint32_t asm0 = smem_u32(As) + aoff;
    const uint32_t asm1 = asm0 + (uint32_t)(HSZ * 2);
    const uint32_t bsm0 = smem_u32(Bs) + boff;
    const uint32_t bsm1 = bsm0 + (uint32_t)(HSZ * 2);

    float acc[2][8][4];
#pragma unroll
    for (int mi = 0; mi < 2; ++mi)
#pragma unroll
        for (int ni = 0; ni < 8; ++ni)
#pragma unroll
            for (int r = 0; r < 4; ++r) acc[mi][ni][r] = 0.f;

    const int nch = K >> 6;
    // prologue: chunk 0 -> buffer 0
#pragma unroll
    for (int i = 0; i < 4; ++i) {
        const int s = fs0 + i;
        cpa16(As + frow * HSTR + s * 8, Ag + s * 8);
        cpa16(Bs + frow * HSTR + s * 8, Bg + s * 8);
    }
    cpa_commit();

    for (int c = 0; c < nch; ++c) {
        cpa_wait0();
        __syncthreads();

        const int cb = c & 1;
        if (c + 1 < nch) {
            const int k0 = (c + 1) << 6;
            __half* an = As + ((c + 1) & 1) * HSZ;
            __half* bn = Bs + ((c + 1) & 1) * HSZ;
#pragma unroll
            for (int i = 0; i < 4; ++i) {
                const int s = fs0 + i;
                cpa16(an + frow * HSTR + s * 8, Ag + k0 + s * 8);
                cpa16(bn + frow * HSTR + s * 8, Bg + k0 + s * 8);
            }
            cpa_commit();
        }

        const uint32_t asmc = cb ? asm1 : asm0;
        const uint32_t bsmc = cb ? bsm1 : bsm0;

#pragma unroll
        for (int kkb = 0; kkb < 4; ++kkb) {           // 4 k16 steps
            uint32_t af[2][4], bf[4][4];
            ldsm4(af[0], asmc + (uint32_t)(kkb * 32));
            ldsm4(af[1], asmc + (uint32_t)(16 * HSTR * 2 + kkb * 32));
#pragma unroll
            for (int p = 0; p < 4; ++p)
                ldsm4(bf[p], bsmc + (uint32_t)(p * 16 * HSTR * 2 + kkb * 32));
#pragma unroll
            for (int mi = 0; mi < 2; ++mi)
#pragma unroll
                for (int p = 0; p < 4; ++p) {
                    MMA_F16(acc[mi][2 * p],     af[mi], bf[p][0], bf[p][1]);
                    MMA_F16(acc[mi][2 * p + 1], af[mi], bf[p][2], bf[p][3]);
                }
        }
    }

#pragma unroll
    for (int mi = 0; mi < 2; ++mi) {
        const int row = row0 + (wm << 5) + (mi << 4) + lr;
#pragma unroll
        for (int ni = 0; ni < 8; ++ni) {
            const int col = col0 + (wn << 6) + (ni << 3) + (lc << 1);
            const float* cc = acc[mi][ni];
            if (OM == 1) {
                __half* Ch = (__half*)Cv;
                *(__half2*)(Ch + (size_t)row * N + col) =
                    __floats2half2_rn(cc[0], cc[1]);
                *(__half2*)(Ch + (size_t)(row + 8) * N + col) =
                    __floats2half2_rn(cc[2], cc[3]);
            } else {
                float* Cf = (float*)Cv;
                *(float2*)(Cf + (size_t)row * N + col) =
                    make_float2(cc[0], cc[1]);
                *(float2*)(Cf + (size_t)(row + 8) * N + col) =
                    make_float2(cc[2], cc[3]);
            }
        }
    }
}

// ---------------------------------------------------------------------------
// FP16 tensor-core causal flash attention (R14 config, unchanged — 155us).
// ---------------------------------------------------------------------------
#define AH_STR 72
#define ATTN_SMEM ((128 * AH_STR + 4 * 64 * AH_STR) * 2)   // 55296 B

__global__ __launch_bounds__(256, 2) void attn_h(const __half* __restrict__ qkv,
                                                 __half* __restrict__ out)
{
    extern __shared__ __half smh2[];
    __half* Ps = smh2;                      // [128][72]: Q staging, then P
    __half* K0 = Ps + 128 * AH_STR;
    __half* K1 = K0 + 64 * AH_STR;
    __half* V0 = K1 + 64 * AH_STR;
    __half* V1 = V0 + 64 * AH_STR;

    const int tid  = threadIdx.x;
    const int lane = tid & 31;
    const int warp = tid >> 5;
    const int lr   = lane >> 2;
    const int lc   = lane & 3;
    const int qb   = gridDim.x - 1 - blockIdx.x;   // heavy tiles first
    const int h    = blockIdx.y;
    const int b    = blockIdx.z;
    const int q0   = qb << 7;
    const int wrow = warp << 4;

    const __half* bb = qkv + (size_t)b * (T_ * TD3) + h * DH;

    const int fr   = tid >> 3;
    const int fseg = (tid & 7) << 3;

#pragma unroll
    for (int p = 0; p < 2; ++p) {
        const int row = fr + p * 32;
        cpa16(K0 + row * AH_STR + fseg, bb + DM     + (size_t)row * TD3 + fseg);
        cpa16(V0 + row * AH_STR + fseg, bb + 2 * DM + (size_t)row * TD3 + fseg);
    }
    cpa_commit();

    const __half2 qs2 = __float2half2_rn(0.1803368867f);
    for (int i = tid; i < 128 * 8; i += 256) {
        const int r  = i >> 3;
        const int c8 = (i & 7) << 3;
        uint4 v = *(const uint4*)(bb + (size_t)(q0 + r) * TD3 + c8);
        __half2* hp = (__half2*)&v;
        hp[0] = __hmul2(hp[0], qs2);
        hp[1] = __hmul2(hp[1], qs2);
        hp[2] = __hmul2(hp[2], qs2);
        hp[3] = __hmul2(hp[3], qs2);
        *(uint4*)(Ps + r * AH_STR + c8) = v;
    }
    __syncthreads();

    uint32_t qf[4][4];
    {
        const uint32_t* qp0 = (const uint32_t*)Ps + (wrow + lr) * 36 + lc;
#pragma unroll
        for (int kkb = 0; kkb < 4; ++kkb) {
            const uint32_t* qp = qp0 + kkb * 8;
            qf[kkb][0] = qp[0];
            qf[kkb][1] = qp[8 * 36];
            qf[kkb][2] = qp[4];
            qf[kkb][3] = qp[8 * 36 + 4];
        }
    }

    const uint32_t k0sm = smem_u32(K0);
    const uint32_t k1sm = smem_u32(K1);
    const uint32_t v0sm = smem_u32(V0);
    const uint32_t v1sm = smem_u32(V1);
    const int l7  = lane & 7;
    const int seg = (lane >> 3) & 1;
    const uint32_t kofs = (uint32_t)((l7 * 36 + seg * 4) * 4);
    const uint32_t vofs = (uint32_t)(((l7 + seg * 8) * 36) * 4);

    float m0 = -1e30f, m1 = -1e30f, l0 = 0.f, l1 = 0.f;
    float oacc[8][4];
#pragma unroll
    for (int ni = 0; ni < 8; ++ni)
#pragma unroll
        for (int r = 0; r < 4; ++r) oacc[ni][r] = 0.f;

    const int gr0 = q0 + wrow + lr;
    const int gr1 = gr0 + 8;
    const int nkt = 2 * qb + 2;

    for (int kt = 0; kt < nkt; ++kt) {
        const int cur = kt & 1;
        cpa_wait0();
        __syncthreads();

        if (kt + 1 < nkt) {
            __half* Kn = (cur ? K0 : K1);
            __half* Vn = (cur ? V0 : V1);
            const int kn0 = (kt + 1) << 6;
#pragma unroll
            for (int p = 0; p < 2; ++p) {
                const int row = fr + p * 32;
                cpa16(Kn + row * AH_STR + fseg,
                      bb + DM     + (size_t)(kn0 + row) * TD3 + fseg);
                cpa16(Vn + row * AH_STR + fseg,
                      bb + 2 * DM + (size_t)(kn0 + row) * TD3 + fseg);
            }
            cpa_commit();
        }

        const uint32_t ksm = (cur ? k1sm : k0sm) + kofs;
        const uint32_t vsm = (cur ? v1sm : v0sm) + vofs;

        float sacc[8][4];
#pragma unroll
        for (int ni = 0; ni < 8; ++ni)
#pragma unroll
            for (int r = 0; r < 4; ++r) sacc[ni][r] = 0.f;

#pragma unroll
        for (int kkb = 0; kkb < 4; ++kkb) {
#pragma unroll
            for (int ni = 0; ni < 8; ++ni) {
                uint32_t b0, b1;
                ldsm2(b0, b1, ksm + (uint32_t)(ni * 1152 + kkb * 32));
                MMA_F16(sacc[ni], qf[kkb], b0, b1);
            }
        }

        if (kt >= 2 * qb) {
            const int k0t = kt << 6;
#pragma unroll
            for (int ni = 0; ni < 8; ++ni) {
                const int cb = k0t + ni * 8 + (lc << 1);
                if (cb     > gr0) sacc[ni][0] = -1e30f;
                if (cb + 1 > gr0) sacc[ni][1] = -1e30f;
                if (cb     > gr1) sacc[ni][2] = -1e30f;
                if (cb + 1 > gr1) sacc[ni][3] = -1e30f;
            }
        }

        float rm0 = -1e30f, rm1 = -1e30f;
#pragma unroll
        for (int ni = 0; ni < 8; ++ni) {
            rm0 = fmaxf(rm0, fmaxf(sacc[ni][0], sacc[ni][1]));
            rm1 = fmaxf(rm1, fmaxf(sacc[ni][2], sacc[ni][3]));
        }
        rm0 = fmaxf(rm0, __shfl_xor_sync(0xffffffffu, rm0, 1, 4));
        rm0 = fmaxf(rm0, __shfl_xor_sync(0xffffffffu, rm0, 2, 4));
        rm1 = fmaxf(rm1, __shfl_xor_sync(0xffffffffu, rm1, 1, 4));
        rm1 = fmaxf(rm1, __shfl_xor_sync(0xffffffffu, rm1, 2, 4));

        const float mn0 = fmaxf(m0, rm0);
        const float mn1 = fmaxf(m1, rm1);
        const float c0f = ex2(m0 - mn0);
        const float c1f = ex2(m1 - mn1);
        m0 = mn0; m1 = mn1;

        float rs0 = 0.f, rs1 = 0.f;
#pragma unroll
        for (int ni = 0; ni < 8; ++ni) {
            sacc[ni][0] = ex2(sacc[ni][0] - mn0);
            sacc[ni][1] = ex2(sacc[ni][1] - mn0);
            sacc[ni][2] = ex2(sacc[ni][2] - mn1);
            sacc[ni][3] = ex2(sacc[ni][3] - mn1);
            rs0 += sacc[ni][0] + sacc[ni][1];
            rs1 += sacc[ni][2] + sacc[ni][3];
        }
        l0 = l0 * c0f + rs0;
        l1 = l1 * c1f + rs1;
#pragma unroll
        for (int ni = 0; ni < 8; ++ni) {
            oacc[ni][0] *= c0f; oacc[ni][1] *= c0f;
            oacc[ni][2] *= c1f; oacc[ni][3] *= c1f;
        }

        {
            uint32_t* pr = (uint32_t*)Ps + (wrow + lr) * 36 + lc;
#pragma unroll
            for (int ni = 0; ni < 8; ++ni) {
                const __half2 a = __floats2half2_rn(sacc[ni][0], sacc[ni][1]);
                const __half2 c = __floats2half2_rn(sacc[ni][2], sacc[ni][3]);
                pr[ni * 4]          = *(const uint32_t*)&a;
                pr[8 * 36 + ni * 4] = *(const uint32_t*)&c;
            }
        }
        __syncwarp();

#pragma unroll
        for (int kkb = 0; kkb < 4; ++kkb) {
            uint32_t pf[4];
            const uint32_t* pp =
                (const uint32_t*)Ps + (wrow + lr) * 36 + kkb * 8 + lc;
            pf[0] = pp[0];
            pf[1] = pp[8 * 36];
            pf[2] = pp[4];
            pf[3] = pp[8 * 36 + 4];
#pragma unroll
            for (int ni = 0; ni < 8; ++ni) {
                uint32_t b0, b1;
                ldsm2t(b0, b1, vsm + (uint32_t)(kkb * 2304 + ni * 16));
                MMA_F16(oacc[ni], pf, b0, b1);
            }
        }
        __syncwarp();
    }

    l0 += __shfl_xor_sync(0xffffffffu, l0, 1, 4);
    l0 += __shfl_xor_sync(0xffffffffu, l0, 2, 4);
    l1 += __shfl_xor_sync(0xffffffffu, l1, 1, 4);
    l1 += __shfl_xor_sync(0xffffffffu, l1, 2, 4);
    const float inv0 = 1.f / l0;
    const float inv1 = 1.f / l1;
    __half* ob = out + (size_t)(b * T_ + gr0) * DM + h * DH + (lc << 1);
#pragma unroll
    for (int ni = 0; ni < 8; ++ni) {
        *(__half2*)(ob + ni * 8) =
            __floats2half2_rn(oacc[ni][0] * inv0, oacc[ni][1] * inv0);
        *(__half2*)(ob + (size_t)8 * DM + ni * 8) =
            __floats2half2_rn(oacc[ni][2] * inv1, oacc[ni][3] * inv1);
    }
}

// ---------------------------------------------------------------------------
extern "C" void kernel_launch(void* const* d_in, const int* in_sizes, int n_in,
                              void* d_out, int out_size)
{
    const float* x     = (const float*)d_in[0];
    const float* w_qkv = (const float*)d_in[1];
    const float* w_out = (const float*)d_in[2];
    float* out = (float*)d_out;

    __half *qkv16, *x16, *wq16, *wo16;
    cudaGetSymbolAddress((void**)&qkv16, g_qkv16);
    cudaGetSymbolAddress((void**)&x16,   g_x16);
    cudaGetSymbolAddress((void**)&wq16,  g_wq16);
    cudaGetSymbolAddress((void**)&wo16,  g_wo16);

    cudaFuncSetAttribute(hgemm<1>,
                         cudaFuncAttributeMaxDynamicSharedMemorySize, HGEMM_SMEM);
    cudaFuncSetAttribute(hgemm<0>,
                         cudaFuncAttributeMaxDynamicSharedMemorySize, HGEMM_SMEM);
    cudaFuncSetAttribute(attn_h,
                         cudaFuncAttributeMaxDynamicSharedMemorySize, ATTN_SMEM);

    // 0) prepasses: x -> fp16; weights -> fp16 transposed [N][K]
    cvt_h<<<(NTOK * DM) / 1024, 256>>>((const float4*)x, (uint2*)x16);
    cvt_ht<<<dim3((3 * DM) / 32, DM / 32), 256>>>(w_qkv, wq16, DM, 3 * DM);
    cvt_ht<<<dim3(DM / 32, DM / 32), 256>>>(w_out, wo16, DM, DM);

    // 1) qkv = x @ w_qkv  (fp16 MMA, k-chunk 64 + ldmatrix.x4; fp16 out)
    hgemm<1><<<dim3((3 * DM) / 128, NTOK / 128), 256, HGEMM_SMEM>>>(
        x16, wq16, qkv16, NTOK, 3 * DM, DM);
    // 2) causal flash attention (unchanged; writes fp16 into x16)
    attn_h<<<dim3(T_ / 128, H_, B_), 256, ATTN_SMEM>>>(qkv16, x16);
    // 3) out = attn @ w_out  (fp16 MMA; final fp32 output)
    hgemm<0><<<dim3(DM / 128, NTOK / 128), 256, HGEMM_SMEM>>>(
        x16, wo16, out, NTOK, DM, DM);
}

// round 16
// speedup vs baseline: 1.1631x; 1.1631x over previous
#include <cuda_runtime.h>
#include <cuda_fp16.h>
#include <cstdint>
#include <cstddef>

#define B_   4
#define T_   2048
#define DM   1024
#define H_   16
#define DH   64
#define NTOK (B_ * T_)   // 8192
#define TD3  (3 * DM)

// Scratch (allocation-free rule: __device__ globals)
__device__ __half g_qkv16[(size_t)NTOK * 3 * DM];  // half qkv
__device__ __half g_x16 [(size_t)NTOK * DM];       // half(x), later half(attn out)
__device__ __half g_wq16[(size_t)3 * DM * DM];     // half(w_qkv^T) [3072][1024]
__device__ __half g_wo16[(size_t)DM * DM];         // half(w_out^T) [1024][1024]

__device__ __forceinline__ void cpa16(const void* s, const void* g) {
    uint32_t sa = (uint32_t)__cvta_generic_to_shared(s);
    asm volatile("cp.async.cg.shared.global [%0], [%1], 16;\n" :: "r"(sa), "l"(g));
}
__device__ __forceinline__ void cpa_commit() {
    asm volatile("cp.async.commit_group;\n");
}
__device__ __forceinline__ void cpa_wait0() {
    asm volatile("cp.async.wait_group 0;\n");
}
__device__ __forceinline__ float ex2(float x) {
    float r;
    asm("ex2.approx.f32 %0, %1;" : "=f"(r) : "f"(x));
    return r;
}
__device__ __forceinline__ uint32_t smem_u32(const void* p) {
    uint32_t a;
    asm("{ .reg .u64 t; cvta.to.shared.u64 t, %1; cvt.u32.u64 %0, t; }"
        : "=r"(a) : "l"(p));
    return a;
}
__device__ __forceinline__ void ldsm2(uint32_t& r0, uint32_t& r1, uint32_t a) {
    asm volatile("ldmatrix.sync.aligned.m8n8.x2.shared.b16 {%0,%1}, [%2];"
                 : "=r"(r0), "=r"(r1) : "r"(a));
}
__device__ __forceinline__ void ldsm2t(uint32_t& r0, uint32_t& r1, uint32_t a) {
    asm volatile("ldmatrix.sync.aligned.m8n8.x2.trans.shared.b16 {%0,%1}, [%2];"
                 : "=r"(r0), "=r"(r1) : "r"(a));
}
__device__ __forceinline__ void ldsm4(uint32_t* r, uint32_t a) {
    asm volatile("ldmatrix.sync.aligned.m8n8.x4.shared.b16 {%0,%1,%2,%3}, [%4];"
                 : "=r"(r[0]), "=r"(r[1]), "=r"(r[2]), "=r"(r[3]) : "r"(a));
}
// fp16 MMA m16n8k16 (fp32 acc)
#define MMA_F16(CC, AF, B0, B1)                                               \
    asm volatile(                                                             \
        "mma.sync.aligned.m16n8k16.row.col.f32.f16.f16.f32 "                  \
        "{%0,%1,%2,%3}, {%4,%5,%6,%7}, {%8,%9}, {%0,%1,%2,%3};"               \
        : "+f"((CC)[0]), "+f"((CC)[1]), "+f"((CC)[2]), "+f"((CC)[3])          \
        : "r"((AF)[0]), "r"((AF)[1]), "r"((AF)[2]), "r"((AF)[3]),             \
          "r"(B0), "r"(B1))

// ---------------------------------------------------------------------------
// Pre-passes.
// ---------------------------------------------------------------------------
__global__ __launch_bounds__(256) void cvt_h(const float4* __restrict__ in,
                                             uint2* __restrict__ out)
{
    const size_t i = (size_t)blockIdx.x * 256 + threadIdx.x;
    const float4 v = in[i];
    const __half2 lo = __floats2half2_rn(v.x, v.y);
    const __half2 hi = __floats2half2_rn(v.z, v.w);
    out[i] = make_uint2(*(const uint32_t*)&lo, *(const uint32_t*)&hi);
}
__global__ __launch_bounds__(256) void cvt_ht(const float* __restrict__ in,
                                              __half* __restrict__ out,
                                              int R, int Cc)
{
    __shared__ float t[32][33];
    const int tx = threadIdx.x & 31, ty = threadIdx.x >> 5;
    const int c0 = blockIdx.x << 5, r0 = blockIdx.y << 5;
#pragma unroll
    for (int i = 0; i < 32; i += 8)
        t[ty + i][tx] = in[(size_t)(r0 + ty + i) * Cc + c0 + tx];
    __syncthreads();
#pragma unroll
    for (int i = 0; i < 32; i += 8)
        out[(size_t)(c0 + ty + i) * R + r0 + tx] = __float2half_rn(t[tx][ty + i]);
}

// ---------------------------------------------------------------------------
// FP16 GEMM v3 = R14 structure (k-chunk 32, HSTR 40, known-good coalesced
// fill) with fragment loads via ldmatrix.x4 (6 per k16-step instead of 24
// scalar LDS.32). Stride-40-half rows: matrix row r starts at bank 20r mod 32
// -> 8 disjoint 4-bank groups, conflict-free per ldmatrix phase.
// OM=1: fp16 output; OM=0: fp32 output.
// ---------------------------------------------------------------------------
#define HSTR 40
#define HSZ  (128 * HSTR)                  // halves per tile
#define HGEMM_SMEM (4 * HSZ * 2)           // 40960 bytes

template<int OM>
__global__ __launch_bounds__(256, 2) void hgemm(const __half* __restrict__ A,
                                                const __half* __restrict__ Bt,
                                                void* __restrict__ Cv,
                                                int M, int N, int K)
{
    extern __shared__ __half smh[];
    __half* As = smh;                      // [2][128][HSTR]
    __half* Bs = smh + 2 * HSZ;            // [2][128][HSTR]

    const int tid  = threadIdx.x;
    const int lane = tid & 31;
    const int warp = tid >> 5;
    const int wm   = warp >> 1;            // 0..3 (32-row blocks)
    const int wn   = warp & 1;             // 0..1 (64-col blocks)
    const int lr   = lane >> 2;
    const int lc   = lane & 3;
    const int row0 = blockIdx.y << 7;
    const int col0 = blockIdx.x << 7;

    // fill (R14 pattern): row = tid>>2 (0..63, +64), seg = (tid&3)*8 halves
    const int frow = tid >> 2;
    const int fch  = (tid & 3) << 3;

    const __half* Ag = A  + (size_t)(row0 + frow) * K + fch;
    const __half* Bg = Bt + (size_t)(col0 + frow) * K + fch;

    // ldmatrix per-lane offsets (bytes)
    const int l7 = lane & 7;
    // A x4: lanes 0-7 (m+l7,k0), 8-15 (m+8+l7,k0), 16-23 (m+l7,k8), 24-31 (m+8+l7,k8)
    const uint32_t aoff = (uint32_t)((wm * 32 + l7 + (((lane >> 3) & 1) << 3)) *
                                     (HSTR * 2) + (((lane >> 4) & 1) << 4));
    // B x4: lanes 0-7 (n+l7,k0), 8-15 (n+l7,k8), 16-23 (n+8+l7,k0), 24-31 (n+8+l7,k8)
    const uint32_t boff = (uint32_t)((wn * 64 + l7 + (((lane >> 4) & 1) << 3)) *
                                     (HSTR * 2) + (((lane >> 3) & 1) << 4));

    const uint32_t asm0 = smem_u32(As) + aoff;
    const uint32_t asm1 = asm0 + (uint32_t)(HSZ * 2);
    const uint32_t bsm0 = smem_u32(Bs) + boff;
    const uint32_t bsm1 = bsm0 + (uint32_t)(HSZ * 2);

    float acc[2][8][4];
#pragma unroll
    for (int mi = 0; mi < 2; ++mi)
#pragma unroll
        for (int ni = 0; ni < 8; ++ni)
#pragma unroll
            for (int r = 0; r < 4; ++r) acc[mi][ni][r] = 0.f;

    const int nch = K >> 5;
    // prologue: chunk 0 -> buffer 0 (R14 coalesced fill)
#pragma unroll
    for (int p = 0; p < 2; ++p) {
        cpa16(As + (frow + p * 64) * HSTR + fch, Ag + (size_t)(p * 64) * K);
        cpa16(Bs + (frow + p * 64) * HSTR + fch, Bg + (size_t)(p * 64) * K);
    }
    cpa_commit();

    for (int c = 0; c < nch; ++c) {
        cpa_wait0();
        __syncthreads();

        const int cb = c & 1;
        if (c + 1 < nch) {
            const int k0 = (c + 1) << 5;
            __half* an = As + ((c + 1) & 1) * HSZ;
            __half* bn = Bs + ((c + 1) & 1) * HSZ;
#pragma unroll
            for (int p = 0; p < 2; ++p) {
                cpa16(an + (frow + p * 64) * HSTR + fch,
                      Ag + k0 + (size_t)(p * 64) * K);
                cpa16(bn + (frow + p * 64) * HSTR + fch,
                      Bg + k0 + (size_t)(p * 64) * K);
            }
            cpa_commit();
        }

        const uint32_t asmc = cb ? asm1 : asm0;
        const uint32_t bsmc = cb ? bsm1 : bsm0;

#pragma unroll
        for (int kkb = 0; kkb < 2; ++kkb) {           // 2 k16 steps
            uint32_t af[2][4], bf[4][4];
            ldsm4(af[0], asmc + (uint32_t)(kkb * 32));
            ldsm4(af[1], asmc + (uint32_t)(16 * HSTR * 2 + kkb * 32));
#pragma unroll
            for (int p = 0; p < 4; ++p)
                ldsm4(bf[p], bsmc + (uint32_t)(p * 16 * HSTR * 2 + kkb * 32));
#pragma unroll
            for (int mi = 0; mi < 2; ++mi)
#pragma unroll
                for (int p = 0; p < 4; ++p) {
                    MMA_F16(acc[mi][2 * p],     af[mi], bf[p][0], bf[p][1]);
                    MMA_F16(acc[mi][2 * p + 1], af[mi], bf[p][2], bf[p][3]);
                }
        }
    }

#pragma unroll
    for (int mi = 0; mi < 2; ++mi) {
        const int row = row0 + (wm << 5) + (mi << 4) + lr;
#pragma unroll
        for (int ni = 0; ni < 8; ++ni) {
            const int col = col0 + (wn << 6) + (ni << 3) + (lc << 1);
            const float* cc = acc[mi][ni];
            if (OM == 1) {
                __half* Ch = (__half*)Cv;
                *(__half2*)(Ch + (size_t)row * N + col) =
                    __floats2half2_rn(cc[0], cc[1]);
                *(__half2*)(Ch + (size_t)(row + 8) * N + col) =
                    __floats2half2_rn(cc[2], cc[3]);
            } else {
                float* Cf = (float*)Cv;
                *(float2*)(Cf + (size_t)row * N + col) =
                    make_float2(cc[0], cc[1]);
                *(float2*)(Cf + (size_t)(row + 8) * N + col) =
                    make_float2(cc[2], cc[3]);
            }
        }
    }
}

// ---------------------------------------------------------------------------
// FP16 tensor-core causal flash attention (R14 config, unchanged — 155us).
// ---------------------------------------------------------------------------
#define AH_STR 72
#define ATTN_SMEM ((128 * AH_STR + 4 * 64 * AH_STR) * 2)   // 55296 B

__global__ __launch_bounds__(256, 2) void attn_h(const __half* __restrict__ qkv,
                                                 __half* __restrict__ out)
{
    extern __shared__ __half smh2[];
    __half* Ps = smh2;                      // [128][72]: Q staging, then P
    __half* K0 = Ps + 128 * AH_STR;
    __half* K1 = K0 + 64 * AH_STR;
    __half* V0 = K1 + 64 * AH_STR;
    __half* V1 = V0 + 64 * AH_STR;

    const int tid  = threadIdx.x;
    const int lane = tid & 31;
    const int warp = tid >> 5;
    const int lr   = lane >> 2;
    const int lc   = lane & 3;
    const int qb   = gridDim.x - 1 - blockIdx.x;   // heavy tiles first
    const int h    = blockIdx.y;
    const int b    = blockIdx.z;
    const int q0   = qb << 7;
    const int wrow = warp << 4;

    const __half* bb = qkv + (size_t)b * (T_ * TD3) + h * DH;

    const int fr   = tid >> 3;
    const int fseg = (tid & 7) << 3;

#pragma unroll
    for (int p = 0; p < 2; ++p) {
        const int row = fr + p * 32;
        cpa16(K0 + row * AH_STR + fseg, bb + DM     + (size_t)row * TD3 + fseg);
        cpa16(V0 + row * AH_STR + fseg, bb + 2 * DM + (size_t)row * TD3 + fseg);
    }
    cpa_commit();

    const __half2 qs2 = __float2half2_rn(0.1803368867f);
    for (int i = tid; i < 128 * 8; i += 256) {
        const int r  = i >> 3;
        const int c8 = (i & 7) << 3;
        uint4 v = *(const uint4*)(bb + (size_t)(q0 + r) * TD3 + c8);
        __half2* hp = (__half2*)&v;
        hp[0] = __hmul2(hp[0], qs2);
        hp[1] = __hmul2(hp[1], qs2);
        hp[2] = __hmul2(hp[2], qs2);
        hp[3] = __hmul2(hp[3], qs2);
        *(uint4*)(Ps + r * AH_STR + c8) = v;
    }
    __syncthreads();

    uint32_t qf[4][4];
    {
        const uint32_t* qp0 = (const uint32_t*)Ps + (wrow + lr) * 36 + lc;
#pragma unroll
        for (int kkb = 0; kkb < 4; ++kkb) {
            const uint32_t* qp = qp0 + kkb * 8;
            qf[kkb][0] = qp[0];
            qf[kkb][1] = qp[8 * 36];
            qf[kkb][2] = qp[4];
            qf[kkb][3] = qp[8 * 36 + 4];
        }
    }

    const uint32_t k0sm = smem_u32(K0);
    const uint32_t k1sm = smem_u32(K1);
    const uint32_t v0sm = smem_u32(V0);
    const uint32_t v1sm = smem_u32(V1);
    const int l7  = lane & 7;
    const int seg = (lane >> 3) & 1;
    const uint32_t kofs = (uint32_t)((l7 * 36 + seg * 4) * 4);
    const uint32_t vofs = (uint32_t)(((l7 + seg * 8) * 36) * 4);

    float m0 = -1e30f, m1 = -1e30f, l0 = 0.f, l1 = 0.f;
    float oacc[8][4];
#pragma unroll
    for (int ni = 0; ni < 8; ++ni)
#pragma unroll
        for (int r = 0; r < 4; ++r) oacc[ni][r] = 0.f;

    const int gr0 = q0 + wrow + lr;
    const int gr1 = gr0 + 8;
    const int nkt = 2 * qb + 2;

    for (int kt = 0; kt < nkt; ++kt) {
        const int cur = kt & 1;
        cpa_wait0();
        __syncthreads();

        if (kt + 1 < nkt) {
            __half* Kn = (cur ? K0 : K1);
            __half* Vn = (cur ? V0 : V1);
            const int kn0 = (kt + 1) << 6;
#pragma unroll
            for (int p = 0; p < 2; ++p) {
                const int row = fr + p * 32;
                cpa16(Kn + row * AH_STR + fseg,
                      bb + DM     + (size_t)(kn0 + row) * TD3 + fseg);
                cpa16(Vn + row * AH_STR + fseg,
                      bb + 2 * DM + (size_t)(kn0 + row) * TD3 + fseg);
            }
            cpa_commit();
        }

        const uint32_t ksm = (cur ? k1sm : k0sm) + kofs;
        const uint32_t vsm = (cur ? v1sm : v0sm) + vofs;

        float sacc[8][4];
#pragma unroll
        for (int ni = 0; ni < 8; ++ni)
#pragma unroll
            for (int r = 0; r < 4; ++r) sacc[ni][r] = 0.f;

#pragma unroll
        for (int kkb = 0; kkb < 4; ++kkb) {
#pragma unroll
            for (int ni = 0; ni < 8; ++ni) {
                uint32_t b0, b1;
                ldsm2(b0, b1, ksm + (uint32_t)(ni * 1152 + kkb * 32));
                MMA_F16(sacc[ni], qf[kkb], b0, b1);
            }
        }

        if (kt >= 2 * qb) {
            const int k0t = kt << 6;
#pragma unroll
            for (int ni = 0; ni < 8; ++ni) {
                const int cb = k0t + ni * 8 + (lc << 1);
                if (cb     > gr0) sacc[ni][0] = -1e30f;
                if (cb + 1 > gr0) sacc[ni][1] = -1e30f;
                if (cb     > gr1) sacc[ni][2] = -1e30f;
                if (cb + 1 > gr1) sacc[ni][3] = -1e30f;
            }
        }

        float rm0 = -1e30f, rm1 = -1e30f;
#pragma unroll
        for (int ni = 0; ni < 8; ++ni) {
            rm0 = fmaxf(rm0, fmaxf(sacc[ni][0], sacc[ni][1]));
            rm1 = fmaxf(rm1, fmaxf(sacc[ni][2], sacc[ni][3]));
        }
        rm0 = fmaxf(rm0, __shfl_xor_sync(0xffffffffu, rm0, 1, 4));
        rm0 = fmaxf(rm0, __shfl_xor_sync(0xffffffffu, rm0, 2, 4));
        rm1 = fmaxf(rm1, __shfl_xor_sync(0xffffffffu, rm1, 1, 4));
        rm1 = fmaxf(rm1, __shfl_xor_sync(0xffffffffu, rm1, 2, 4));

        const float mn0 = fmaxf(m0, rm0);
        const float mn1 = fmaxf(m1, rm1);
        const float c0f = ex2(m0 - mn0);
        const float c1f = ex2(m1 - mn1);
        m0 = mn0; m1 = mn1;

        float rs0 = 0.f, rs1 = 0.f;
#pragma unroll
        for (int ni = 0; ni < 8; ++ni) {
            sacc[ni][0] = ex2(sacc[ni][0] - mn0);
            sacc[ni][1] = ex2(sacc[ni][1] - mn0);
            sacc[ni][2] = ex2(sacc[ni][2] - mn1);
            sacc[ni][3] = ex2(sacc[ni][3] - mn1);
            rs0 += sacc[ni][0] + sacc[ni][1];
            rs1 += sacc[ni][2] + sacc[ni][3];
        }
        l0 = l0 * c0f + rs0;
        l1 = l1 * c1f + rs1;
#pragma unroll
        for (int ni = 0; ni < 8; ++ni) {
            oacc[ni][0] *= c0f; oacc[ni][1] *= c0f;
            oacc[ni][2] *= c1f; oacc[ni][3] *= c1f;
        }

        {
            uint32_t* pr = (uint32_t*)Ps + (wrow + lr) * 36 + lc;
#pragma unroll
            for (int ni = 0; ni < 8; ++ni) {
                const __half2 a = __floats2half2_rn(sacc[ni][0], sacc[ni][1]);
                const __half2 c = __floats2half2_rn(sacc[ni][2], sacc[ni][3]);
                pr[ni * 4]          = *(const uint32_t*)&a;
                pr[8 * 36 + ni * 4] = *(const uint32_t*)&c;
            }
        }
        __syncwarp();

#pragma unroll
        for (int kkb = 0; kkb < 4; ++kkb) {
            uint32_t pf[4];
            const uint32_t* pp =
                (const uint32_t*)Ps + (wrow + lr) * 36 + kkb * 8 + lc;
            pf[0] = pp[0];
            pf[1] = pp[8 * 36];
            pf[2] = pp[4];
            pf[3] = pp[8 * 36 + 4];
#pragma unroll
            for (int ni = 0; ni < 8; ++ni) {
                uint32_t b0, b1;
                ldsm2t(b0, b1, vsm + (uint32_t)(kkb * 2304 + ni * 16));
                MMA_F16(oacc[ni], pf, b0, b1);
            }
        }
        __syncwarp();
    }

    l0 += __shfl_xor_sync(0xffffffffu, l0, 1, 4);
    l0 += __shfl_xor_sync(0xffffffffu, l0, 2, 4);
    l1 += __shfl_xor_sync(0xffffffffu, l1, 1, 4);
    l1 += __shfl_xor_sync(0xffffffffu, l1, 2, 4);
    const float inv0 = 1.f / l0;
    const float inv1 = 1.f / l1;
    __half* ob = out + (size_t)(b * T_ + gr0) * DM + h * DH + (lc << 1);
#pragma unroll
    for (int ni = 0; ni < 8; ++ni) {
        *(__half2*)(ob + ni * 8) =
            __floats2half2_rn(oacc[ni][0] * inv0, oacc[ni][1] * inv0);
        *(__half2*)(ob + (size_t)8 * DM + ni * 8) =
            __floats2half2_rn(oacc[ni][2] * inv1, oacc[ni][3] * inv1);
    }
}

// ---------------------------------------------------------------------------
extern "C" void kernel_launch(void* const* d_in, const int* in_sizes, int n_in,
                              void* d_out, int out_size)
{
    const float* x     = (const float*)d_in[0];
    const float* w_qkv = (const float*)d_in[1];
    const float* w_out = (const float*)d_in[2];
    float* out = (float*)d_out;

    __half *qkv16, *x16, *wq16, *wo16;
    cudaGetSymbolAddress((void**)&qkv16, g_qkv16);
    cudaGetSymbolAddress((void**)&x16,   g_x16);
    cudaGetSymbolAddress((void**)&wq16,  g_wq16);
    cudaGetSymbolAddress((void**)&wo16,  g_wo16);

    cudaFuncSetAttribute(hgemm<1>,
                         cudaFuncAttributeMaxDynamicSharedMemorySize, HGEMM_SMEM);
    cudaFuncSetAttribute(hgemm<0>,
                         cudaFuncAttributeMaxDynamicSharedMemorySize, HGEMM_SMEM);
    cudaFuncSetAttribute(attn_h,
                         cudaFuncAttributeMaxDynamicSharedMemorySize, ATTN_SMEM);

    // 0) prepasses: x -> fp16; weights -> fp16 transposed [N][K]
    cvt_h<<<(NTOK * DM) / 1024, 256>>>((const float4*)x, (uint2*)x16);
    cvt_ht<<<dim3((3 * DM) / 32, DM / 32), 256>>>(w_qkv, wq16, DM, 3 * DM);
    cvt_ht<<<dim3(DM / 32, DM / 32), 256>>>(w_out, wo16, DM, DM);

    // 1) qkv = x @ w_qkv  (fp16 MMA, R14 fill + ldmatrix.x4 frags; fp16 out)
    hgemm<1><<<dim3((3 * DM) / 128, NTOK / 128), 256, HGEMM_SMEM>>>(
        x16, wq16, qkv16, NTOK, 3 * DM, DM);
    // 2) causal flash attention (unchanged; writes fp16 into x16)
    attn_h<<<dim3(T_ / 128, H_, B_), 256, ATTN_SMEM>>>(qkv16, x16);
    // 3) out = attn @ w_out  (fp16 MMA; final fp32 output)
    hgemm<0><<<dim3(DM / 128, NTOK / 128), 256, HGEMM_SMEM>>>(
        x16, wo16, out, NTOK, DM, DM);
}

// round 17
// speedup vs baseline: 1.1997x; 1.0315x over previous
#include <cuda_runtime.h>
#include <cuda_fp16.h>
#include <cstdint>
#include <cstddef>

#define B_   4
#define T_   2048
#define DM   1024
#define H_   16
#define DH   64
#define NTOK (B_ * T_)   // 8192
#define TD3  (3 * DM)

// Scratch (allocation-free rule: __device__ globals)
__device__ __half g_qkv16[(size_t)NTOK * 3 * DM];  // half qkv
__device__ __half g_x16 [(size_t)NTOK * DM];       // half(x), later half(attn out)
__device__ __half g_wq16[(size_t)3 * DM * DM];     // half(w_qkv^T) [3072][1024]
__device__ __half g_wo16[(size_t)DM * DM];         // half(w_out^T) [1024][1024]

__device__ __forceinline__ void cpa16(const void* s, const void* g) {
    uint32_t sa = (uint32_t)__cvta_generic_to_shared(s);
    asm volatile("cp.async.cg.shared.global [%0], [%1], 16;\n" :: "r"(sa), "l"(g));
}
__device__ __forceinline__ void cpa_commit() {
    asm volatile("cp.async.commit_group;\n");
}
__device__ __forceinline__ void cpa_wait0() {
    asm volatile("cp.async.wait_group 0;\n");
}
__device__ __forceinline__ float ex2(float x) {
    float r;
    asm("ex2.approx.f32 %0, %1;" : "=f"(r) : "f"(x));
    return r;
}
__device__ __forceinline__ uint32_t smem_u32(const void* p) {
    uint32_t a;
    asm("{ .reg .u64 t; cvta.to.shared.u64 t, %1; cvt.u32.u64 %0, t; }"
        : "=r"(a) : "l"(p));
    return a;
}
__device__ __forceinline__ void ldsm2(uint32_t& r0, uint32_t& r1, uint32_t a) {
    asm volatile("ldmatrix.sync.aligned.m8n8.x2.shared.b16 {%0,%1}, [%2];"
                 : "=r"(r0), "=r"(r1) : "r"(a));
}
__device__ __forceinline__ void ldsm2t(uint32_t& r0, uint32_t& r1, uint32_t a) {
    asm volatile("ldmatrix.sync.aligned.m8n8.x2.trans.shared.b16 {%0,%1}, [%2];"
                 : "=r"(r0), "=r"(r1) : "r"(a));
}
__device__ __forceinline__ void ldsm4(uint32_t* r, uint32_t a) {
    asm volatile("ldmatrix.sync.aligned.m8n8.x4.shared.b16 {%0,%1,%2,%3}, [%4];"
                 : "=r"(r[0]), "=r"(r[1]), "=r"(r[2]), "=r"(r[3]) : "r"(a));
}
// fp16 MMA m16n8k16 (fp32 acc)
#define MMA_F16(CC, AF, B0, B1)                                               \
    asm volatile(                                                             \
        "mma.sync.aligned.m16n8k16.row.col.f32.f16.f16.f32 "                  \
        "{%0,%1,%2,%3}, {%4,%5,%6,%7}, {%8,%9}, {%0,%1,%2,%3};"               \
        : "+f"((CC)[0]), "+f"((CC)[1]), "+f"((CC)[2]), "+f"((CC)[3])          \
        : "r"((AF)[0]), "r"((AF)[1]), "r"((AF)[2]), "r"((AF)[3]),             \
          "r"(B0), "r"(B1))

// ---------------------------------------------------------------------------
// Pre-passes.
// ---------------------------------------------------------------------------
__global__ __launch_bounds__(256) void cvt_h(const float4* __restrict__ in,
                                             uint2* __restrict__ out)
{
    const size_t i = (size_t)blockIdx.x * 256 + threadIdx.x;
    const float4 v = in[i];
    const __half2 lo = __floats2half2_rn(v.x, v.y);
    const __half2 hi = __floats2half2_rn(v.z, v.w);
    out[i] = make_uint2(*(const uint32_t*)&lo, *(const uint32_t*)&hi);
}
__global__ __launch_bounds__(256) void cvt_ht(const float* __restrict__ in,
                                              __half* __restrict__ out,
                                              int R, int Cc)
{
    __shared__ float t[32][33];
    const int tx = threadIdx.x & 31, ty = threadIdx.x >> 5;
    const int c0 = blockIdx.x << 5, r0 = blockIdx.y << 5;
#pragma unroll
    for (int i = 0; i < 32; i += 8)
        t[ty + i][tx] = in[(size_t)(r0 + ty + i) * Cc + c0 + tx];
    __syncthreads();
#pragma unroll
    for (int i = 0; i < 32; i += 8)
        out[(size_t)(c0 + ty + i) * R + r0 + tx] = __float2half_rn(t[tx][ty + i]);
}

// ---------------------------------------------------------------------------
// FP16 GEMM v4: R16 fragment path (ldmatrix.x4, validated) + K-CHUNK 64 with
// SECTOR-COALESCED fill (8 threads cover each row's 128B contiguously —
// every 32B L2 sector fully used; this is what R15 got wrong).
// HSTR 72: row start bank = 4r mod 32 -> 8 disjoint 4-bank groups,
// ldmatrix conflict-free; fill phases are 128B-contiguous.
// Half the barriers of the k32 version. OM=1: fp16 out; OM=0: fp32 out.
// ---------------------------------------------------------------------------
#define HSTR 72
#define HSZ  (128 * HSTR)                   // halves per tile
#define HGEMM_SMEM (4 * HSZ * 2)            // 73728 bytes (2 CTAs/SM)

template<int OM>
__global__ __launch_bounds__(256, 2) void hgemm(const __half* __restrict__ A,
                                                const __half* __restrict__ Bt,
                                                void* __restrict__ Cv,
                                                int M, int N, int K)
{
    extern __shared__ __half smh[];
    __half* As = smh;                      // [2][128][HSTR]
    __half* Bs = smh + 2 * HSZ;            // [2][128][HSTR]

    const int tid  = threadIdx.x;
    const int lane = tid & 31;
    const int warp = tid >> 5;
    const int wm   = warp >> 1;            // 0..3 (32-row blocks)
    const int wn   = warp & 1;             // 0..1 (64-col blocks)
    const int lr   = lane >> 2;
    const int lc   = lane & 3;
    const int row0 = blockIdx.y << 7;
    const int col0 = blockIdx.x << 7;

    // fill: 8 threads per row cover its 128B contiguously; 4 passes of 32 rows
    const int frow = tid >> 3;             // 0..31
    const int fch  = (tid & 7) << 3;       // half offset 0..56

    const __half* Ag = A  + (size_t)(row0 + frow) * K + fch;
    const __half* Bg = Bt + (size_t)(col0 + frow) * K + fch;

    // ldmatrix per-lane offsets (bytes) — validated mapping from R16
    const int l7 = lane & 7;
    const uint32_t aoff = (uint32_t)((wm * 32 + l7 + (((lane >> 3) & 1) << 3)) *
                                     (HSTR * 2) + (((lane >> 4) & 1) << 4));
    const uint32_t boff = (uint32_t)((wn * 64 + l7 + (((lane >> 4) & 1) << 3)) *
                                     (HSTR * 2) + (((lane >> 3) & 1) << 4));

    const uint32_t asm0 = smem_u32(As) + aoff;
    const uint32_t asm1 = asm0 + (uint32_t)(HSZ * 2);
    const uint32_t bsm0 = smem_u32(Bs) + boff;
    const uint32_t bsm1 = bsm0 + (uint32_t)(HSZ * 2);

    float acc[2][8][4];
#pragma unroll
    for (int mi = 0; mi < 2; ++mi)
#pragma unroll
        for (int ni = 0; ni < 8; ++ni)
#pragma unroll
            for (int r = 0; r < 4; ++r) acc[mi][ni][r] = 0.f;

    const int nch = K >> 6;
    // prologue: chunk 0 -> buffer 0
#pragma unroll
    for (int p = 0; p < 4; ++p) {
        const int row = frow + p * 32;
        cpa16(As + row * HSTR + fch, Ag + (size_t)(p * 32) * K);
        cpa16(Bs + row * HSTR + fch, Bg + (size_t)(p * 32) * K);
    }
    cpa_commit();

    for (int c = 0; c < nch; ++c) {
        cpa_wait0();
        __syncthreads();

        const int cb = c & 1;
        if (c + 1 < nch) {
            const int k0 = (c + 1) << 6;
            __half* an = As + ((c + 1) & 1) * HSZ;
            __half* bn = Bs + ((c + 1) & 1) * HSZ;
#pragma unroll
            for (int p = 0; p < 4; ++p) {
                const int row = frow + p * 32;
                cpa16(an + row * HSTR + fch, Ag + k0 + (size_t)(p * 32) * K);
                cpa16(bn + row * HSTR + fch, Bg + k0 + (size_t)(p * 32) * K);
            }
            cpa_commit();
        }

        const uint32_t asmc = cb ? asm1 : asm0;
        const uint32_t bsmc = cb ? bsm1 : bsm0;

#pragma unroll
        for (int kkb = 0; kkb < 4; ++kkb) {           // 4 k16 steps
            uint32_t af[2][4], bf[4][4];
            ldsm4(af[0], asmc + (uint32_t)(kkb * 32));
            ldsm4(af[1], asmc + (uint32_t)(16 * HSTR * 2 + kkb * 32));
#pragma unroll
            for (int p = 0; p < 4; ++p)
                ldsm4(bf[p], bsmc + (uint32_t)(p * 16 * HSTR * 2 + kkb * 32));
#pragma unroll
            for (int mi = 0; mi < 2; ++mi)
#pragma unroll
                for (int p = 0; p < 4; ++p) {
                    MMA_F16(acc[mi][2 * p],     af[mi], bf[p][0], bf[p][1]);
                    MMA_F16(acc[mi][2 * p + 1], af[mi], bf[p][2], bf[p][3]);
                }
        }
    }

#pragma unroll
    for (int mi = 0; mi < 2; ++mi) {
        const int row = row0 + (wm << 5) + (mi << 4) + lr;
#pragma unroll
        for (int ni = 0; ni < 8; ++ni) {
            const int col = col0 + (wn << 6) + (ni << 3) + (lc << 1);
            const float* cc = acc[mi][ni];
            if (OM == 1) {
                __half* Ch = (__half*)Cv;
                *(__half2*)(Ch + (size_t)row * N + col) =
                    __floats2half2_rn(cc[0], cc[1]);
                *(__half2*)(Ch + (size_t)(row + 8) * N + col) =
                    __floats2half2_rn(cc[2], cc[3]);
            } else {
                float* Cf = (float*)Cv;
                *(float2*)(Cf + (size_t)row * N + col) =
                    make_float2(cc[0], cc[1]);
                *(float2*)(Cf + (size_t)(row + 8) * N + col) =
                    make_float2(cc[2], cc[3]);
            }
        }
    }
}

// ---------------------------------------------------------------------------
// FP16 tensor-core causal flash attention (R14 config, unchanged — 155us).
// ---------------------------------------------------------------------------
#define AH_STR 72
#define ATTN_SMEM ((128 * AH_STR + 4 * 64 * AH_STR) * 2)   // 55296 B

__global__ __launch_bounds__(256, 2) void attn_h(const __half* __restrict__ qkv,
                                                 __half* __restrict__ out)
{
    extern __shared__ __half smh2[];
    __half* Ps = smh2;                      // [128][72]: Q staging, then P
    __half* K0 = Ps + 128 * AH_STR;
    __half* K1 = K0 + 64 * AH_STR;
    __half* V0 = K1 + 64 * AH_STR;
    __half* V1 = V0 + 64 * AH_STR;

    const int tid  = threadIdx.x;
    const int lane = tid & 31;
    const int warp = tid >> 5;
    const int lr   = lane >> 2;
    const int lc   = lane & 3;
    const int qb   = gridDim.x - 1 - blockIdx.x;   // heavy tiles first
    const int h    = blockIdx.y;
    const int b    = blockIdx.z;
    const int q0   = qb << 7;
    const int wrow = warp << 4;

    const __half* bb = qkv + (size_t)b * (T_ * TD3) + h * DH;

    const int fr   = tid >> 3;
    const int fseg = (tid & 7) << 3;

#pragma unroll
    for (int p = 0; p < 2; ++p) {
        const int row = fr + p * 32;
        cpa16(K0 + row * AH_STR + fseg, bb + DM     + (size_t)row * TD3 + fseg);
        cpa16(V0 + row * AH_STR + fseg, bb + 2 * DM + (size_t)row * TD3 + fseg);
    }
    cpa_commit();

    const __half2 qs2 = __float2half2_rn(0.1803368867f);
    for (int i = tid; i < 128 * 8; i += 256) {
        const int r  = i >> 3;
        const int c8 = (i & 7) << 3;
        uint4 v = *(const uint4*)(bb + (size_t)(q0 + r) * TD3 + c8);
        __half2* hp = (__half2*)&v;
        hp[0] = __hmul2(hp[0], qs2);
        hp[1] = __hmul2(hp[1], qs2);
        hp[2] = __hmul2(hp[2], qs2);
        hp[3] = __hmul2(hp[3], qs2);
        *(uint4*)(Ps + r * AH_STR + c8) = v;
    }
    __syncthreads();

    uint32_t qf[4][4];
    {
        const uint32_t* qp0 = (const uint32_t*)Ps + (wrow + lr) * 36 + lc;
#pragma unroll
        for (int kkb = 0; kkb < 4; ++kkb) {
            const uint32_t* qp = qp0 + kkb * 8;
            qf[kkb][0] = qp[0];
            qf[kkb][1] = qp[8 * 36];
            qf[kkb][2] = qp[4];
            qf[kkb][3] = qp[8 * 36 + 4];
        }
    }

    const uint32_t k0sm = smem_u32(K0);
    const uint32_t k1sm = smem_u32(K1);
    const uint32_t v0sm = smem_u32(V0);
    const uint32_t v1sm = smem_u32(V1);
    const int l7  = lane & 7;
    const int seg = (lane >> 3) & 1;
    const uint32_t kofs = (uint32_t)((l7 * 36 + seg * 4) * 4);
    const uint32_t vofs = (uint32_t)(((l7 + seg * 8) * 36) * 4);

    float m0 = -1e30f, m1 = -1e30f, l0 = 0.f, l1 = 0.f;
    float oacc[8][4];
#pragma unroll
    for (int ni = 0; ni < 8; ++ni)
#pragma unroll
        for (int r = 0; r < 4; ++r) oacc[ni][r] = 0.f;

    const int gr0 = q0 + wrow + lr;
    const int gr1 = gr0 + 8;
    const int nkt = 2 * qb + 2;

    for (int kt = 0; kt < nkt; ++kt) {
        const int cur = kt & 1;
        cpa_wait0();
        __syncthreads();

        if (kt + 1 < nkt) {
            __half* Kn = (cur ? K0 : K1);
            __half* Vn = (cur ? V0 : V1);
            const int kn0 = (kt + 1) << 6;
#pragma unroll
            for (int p = 0; p < 2; ++p) {
                const int row = fr + p * 32;
                cpa16(Kn + row * AH_STR + fseg,
                      bb + DM     + (size_t)(kn0 + row) * TD3 + fseg);
                cpa16(Vn + row * AH_STR + fseg,
                      bb + 2 * DM + (size_t)(kn0 + row) * TD3 + fseg);
            }
            cpa_commit();
        }

        const uint32_t ksm = (cur ? k1sm : k0sm) + kofs;
        const uint32_t vsm = (cur ? v1sm : v0sm) + vofs;

        float sacc[8][4];
#pragma unroll
        for (int ni = 0; ni < 8; ++ni)
#pragma unroll
            for (int r = 0; r < 4; ++r) sacc[ni][r] = 0.f;

#pragma unroll
        for (int kkb = 0; kkb < 4; ++kkb) {
#pragma unroll
            for (int ni = 0; ni < 8; ++ni) {
                uint32_t b0, b1;
                ldsm2(b0, b1, ksm + (uint32_t)(ni * 1152 + kkb * 32));
                MMA_F16(sacc[ni], qf[kkb], b0, b1);
            }
        }

        if (kt >= 2 * qb) {
            const int k0t = kt << 6;
#pragma unroll
            for (int ni = 0; ni < 8; ++ni) {
                const int cb = k0t + ni * 8 + (lc << 1);
                if (cb     > gr0) sacc[ni][0] = -1e30f;
                if (cb + 1 > gr0) sacc[ni][1] = -1e30f;
                if (cb     > gr1) sacc[ni][2] = -1e30f;
                if (cb + 1 > gr1) sacc[ni][3] = -1e30f;
            }
        }

        float rm0 = -1e30f, rm1 = -1e30f;
#pragma unroll
        for (int ni = 0; ni < 8; ++ni) {
            rm0 = fmaxf(rm0, fmaxf(sacc[ni][0], sacc[ni][1]));
            rm1 = fmaxf(rm1, fmaxf(sacc[ni][2], sacc[ni][3]));
        }
        rm0 = fmaxf(rm0, __shfl_xor_sync(0xffffffffu, rm0, 1, 4));
        rm0 = fmaxf(rm0, __shfl_xor_sync(0xffffffffu, rm0, 2, 4));
        rm1 = fmaxf(rm1, __shfl_xor_sync(0xffffffffu, rm1, 1, 4));
        rm1 = fmaxf(rm1, __shfl_xor_sync(0xffffffffu, rm1, 2, 4));

        const float mn0 = fmaxf(m0, rm0);
        const float mn1 = fmaxf(m1, rm1);
        const float c0f = ex2(m0 - mn0);
        const float c1f = ex2(m1 - mn1);
        m0 = mn0; m1 = mn1;

        float rs0 = 0.f, rs1 = 0.f;
#pragma unroll
        for (int ni = 0; ni < 8; ++ni) {
            sacc[ni][0] = ex2(sacc[ni][0] - mn0);
            sacc[ni][1] = ex2(sacc[ni][1] - mn0);
            sacc[ni][2] = ex2(sacc[ni][2] - mn1);
            sacc[ni][3] = ex2(sacc[ni][3] - mn1);
            rs0 += sacc[ni][0] + sacc[ni][1];
            rs1 += sacc[ni][2] + sacc[ni][3];
        }
        l0 = l0 * c0f + rs0;
        l1 = l1 * c1f + rs1;
#pragma unroll
        for (int ni = 0; ni < 8; ++ni) {
            oacc[ni][0] *= c0f; oacc[ni][1] *= c0f;
            oacc[ni][2] *= c1f; oacc[ni][3] *= c1f;
        }

        {
            uint32_t* pr = (uint32_t*)Ps + (wrow + lr) * 36 + lc;
#pragma unroll
            for (int ni = 0; ni < 8; ++ni) {
                const __half2 a = __floats2half2_rn(sacc[ni][0], sacc[ni][1]);
                const __half2 c = __floats2half2_rn(sacc[ni][2], sacc[ni][3]);
                pr[ni * 4]          = *(const uint32_t*)&a;
                pr[8 * 36 + ni * 4] = *(const uint32_t*)&c;
            }
        }
        __syncwarp();

#pragma unroll
        for (int kkb = 0; kkb < 4; ++kkb) {
            uint32_t pf[4];
            const uint32_t* pp =
                (const uint32_t*)Ps + (wrow + lr) * 36 + kkb * 8 + lc;
            pf[0] = pp[0];
            pf[1] = pp[8 * 36];
            pf[2] = pp[4];
            pf[3] = pp[8 * 36 + 4];
#pragma unroll
            for (int ni = 0; ni < 8; ++ni) {
                uint32_t b0, b1;
                ldsm2t(b0, b1, vsm + (uint32_t)(kkb * 2304 + ni * 16));
                MMA_F16(oacc[ni], pf, b0, b1);
            }
        }
        __syncwarp();
    }

    l0 += __shfl_xor_sync(0xffffffffu, l0, 1, 4);
    l0 += __shfl_xor_sync(0xffffffffu, l0, 2, 4);
    l1 += __shfl_xor_sync(0xffffffffu, l1, 1, 4);
    l1 += __shfl_xor_sync(0xffffffffu, l1, 2, 4);
    const float inv0 = 1.f / l0;
    const float inv1 = 1.f / l1;
    __half* ob = out + (size_t)(b * T_ + gr0) * DM + h * DH + (lc << 1);
#pragma unroll
    for (int ni = 0; ni < 8; ++ni) {
        *(__half2*)(ob + ni * 8) =
            __floats2half2_rn(oacc[ni][0] * inv0, oacc[ni][1] * inv0);
        *(__half2*)(ob + (size_t)8 * DM + ni * 8) =
            __floats2half2_rn(oacc[ni][2] * inv1, oacc[ni][3] * inv1);
    }
}

// ---------------------------------------------------------------------------
extern "C" void kernel_launch(void* const* d_in, const int* in_sizes, int n_in,
                              void* d_out, int out_size)
{
    const float* x     = (const float*)d_in[0];
    const float* w_qkv = (const float*)d_in[1];
    const float* w_out = (const float*)d_in[2];
    float* out = (float*)d_out;

    __half *qkv16, *x16, *wq16, *wo16;
    cudaGetSymbolAddress((void**)&qkv16, g_qkv16);
    cudaGetSymbolAddress((void**)&x16,   g_x16);
    cudaGetSymbolAddress((void**)&wq16,  g_wq16);
    cudaGetSymbolAddress((void**)&wo16,  g_wo16);

    cudaFuncSetAttribute(hgemm<1>,
                         cudaFuncAttributeMaxDynamicSharedMemorySize, HGEMM_SMEM);
    cudaFuncSetAttribute(hgemm<0>,
                         cudaFuncAttributeMaxDynamicSharedMemorySize, HGEMM_SMEM);
    cudaFuncSetAttribute(attn_h,
                         cudaFuncAttributeMaxDynamicSharedMemorySize, ATTN_SMEM);

    // 0) prepasses: x -> fp16; weights -> fp16 transposed [N][K]
    cvt_h<<<(NTOK * DM) / 1024, 256>>>((const float4*)x, (uint2*)x16);
    cvt_ht<<<dim3((3 * DM) / 32, DM / 32), 256>>>(w_qkv, wq16, DM, 3 * DM);
    cvt_ht<<<dim3(DM / 32, DM / 32), 256>>>(w_out, wo16, DM, DM);

    // 1) qkv = x @ w_qkv  (fp16, k-chunk 64, coalesced fill, ldmatrix.x4)
    hgemm<1><<<dim3((3 * DM) / 128, NTOK / 128), 256, HGEMM_SMEM>>>(
        x16, wq16, qkv16, NTOK, 3 * DM, DM);
    // 2) causal flash attention (unchanged; writes fp16 into x16)
    attn_h<<<dim3(T_ / 128, H_, B_), 256, ATTN_SMEM>>>(qkv16, x16);
    // 3) out = attn @ w_out  (fp16; final fp32 output)
    hgemm<0><<<dim3(DM / 128, NTOK / 128), 256, HGEMM_SMEM>>>(
        x16, wo16, out, NTOK, DM, DM);
}